// round 4
// baseline (speedup 1.0000x reference)
#include <cuda_runtime.h>
#include <math.h>

#define NN 10000
#define EE 160000
#define ET (EE + NN)
#define EIN 16
#define HID 128
#define HEADS 4
#define NEGS 0.2f

typedef unsigned long long u64;

// ---------------- f32x2 helpers (pure register ops) ----------------
__device__ __forceinline__ u64 dupf(float v) {
    u64 r; unsigned u = __float_as_uint(v);
    asm("mov.b64 %0, {%1,%2};" : "=l"(r) : "r"(u), "r"(u));
    return r;
}
__device__ __forceinline__ void upk(u64 p, float& lo, float& hi) {
    unsigned a, b;
    asm("mov.b64 {%0,%1}, %2;" : "=r"(a), "=r"(b) : "l"(p));
    lo = __uint_as_float(a); hi = __uint_as_float(b);
}
__device__ __forceinline__ u64 fma2(u64 a, u64 b, u64 c) {
    u64 d; asm("fma.rn.f32x2 %0, %1, %2, %3;" : "=l"(d) : "l"(a), "l"(b), "l"(c));
    return d;
}
__device__ __forceinline__ u64 add2(u64 a, u64 b) {
    u64 d; asm("add.rn.f32x2 %0, %1, %2;" : "=l"(d) : "l"(a), "l"(b));
    return d;
}
__device__ __forceinline__ u64 mul2(u64 a, u64 b) {
    u64 d; asm("mul.rn.f32x2 %0, %1, %2;" : "=l"(d) : "l"(a), "l"(b));
    return d;
}
// global loads of data produced by EARLIER kernels only
__device__ __forceinline__ void ldg2(const void* p, u64& a, u64& b) {
    asm("ld.global.v2.u64 {%0,%1}, [%2];" : "=l"(a), "=l"(b) : "l"(p));
}
__device__ __forceinline__ u64 ldg1(const void* p) {
    u64 a; asm("ld.global.u64 %0, [%1];" : "=l"(a) : "l"(p));
    return a;
}

// ---------------- scratch ----------------
__device__ float g_h[2][NN * HID];
__device__ float g_xlr[NN * 1024];
__device__ float g_asum[NN * EIN];
__device__ int   g_deg[NN];
__device__ float g_selfA[NN * 17];
__device__ int   g_rowptr[NN + 1];
__device__ int   g_cursor[NN];
__device__ int   g_src[ET];
__device__ int   g_eids[ET];
__device__ __align__(16) u64 g_ea2[(size_t)ET * 18];   // dup'd f32x2 edge coeffs, CSR order
__device__ float g_M[3 * 17 * 512];

// ---------------- fused preprocessing #1: zero + compose + node-embedding ----------------
#define ZB 1250          // 1250*128 = 160000 = NN*EIN
#define CB 204           // 204*128 = 26112 = 3*17*512
#define EB 625           // 625*16  = 10000

__global__ void __launch_bounds__(128) k_pre(const float* __restrict__ x,
                                             const float* __restrict__ Wn,
                                             const float* __restrict__ bn,
                                             const float* __restrict__ edge_W,
                                             const float* __restrict__ edge_b,
                                             const float* __restrict__ We) {
    __shared__ float xs[16][64];
    int b = blockIdx.x, tid = threadIdx.x;
    if (b < ZB) {
        int i = b * 128 + tid;
        g_asum[i] = 0.f;
        if (i < NN) { g_deg[i] = 0; g_cursor[i] = 0; }
        return;
    }
    if (b < ZB + CB) {
        int idx = (b - ZB) * 128 + tid;
        int l = idx / (17 * 512);
        int r = idx - l * (17 * 512);
        int k = r >> 9;
        int j = r & 511;
        const float* wp = We + l * 128 * 512 + j;
        float acc = 0.f;
#pragma unroll 8
        for (int t = 0; t < 128; t++) {
            float ev = (k < 16) ? edge_W[k * 128 + t] : edge_b[t];
            acc += ev * wp[t * 512];
        }
        g_M[idx] = acc;
        return;
    }
    int nb = (b - ZB - CB) * 16;
#pragma unroll
    for (int i = 0; i < 8; i++) {
        int idx = tid + i * 128;
        int r = idx >> 6, c = idx & 63;
        xs[r][c] = x[(nb + r) * 64 + c];
    }
    __syncthreads();
    int c = tid;
    float acc[16];
#pragma unroll
    for (int n = 0; n < 16; n++) acc[n] = 0.f;
    for (int k = 0; k < 64; k++) {
        float wv = Wn[k * 128 + c];
#pragma unroll
        for (int n = 0; n < 16; n++) acc[n] += xs[n][k] * wv;
    }
    float bb = bn[c];
#pragma unroll
    for (int n = 0; n < 16; n++)
        g_h[0][(nb + n) * 128 + c] = acc[n] + bb;
}

// ---------------- degree + edge_attr segment sums ----------------
__global__ void k_deg(const float* __restrict__ eattr, const int* __restrict__ eidx) {
    int i = blockIdx.x * blockDim.x + threadIdx.x;
    if (i >= EE * EIN) return;
    int e = i >> 4, k = i & 15;
    int d = eidx[EE + e];
    atomicAdd(&g_asum[d * EIN + k], eattr[i]);
    if (k == 0) atomicAdd(&g_deg[d], 1);
}

__global__ void k_scan() {
    __shared__ int sums[1024];
    int t = threadIdx.x;
    const int CH = 10;
    int base = t * CH;
    int local[CH];
    int run = 0;
#pragma unroll
    for (int i = 0; i < CH; i++) {
        int gi = base + i;
        int v = (gi < NN) ? (g_deg[gi] + 1) : 0;
        local[i] = run;
        run += v;
    }
    sums[t] = run;
    __syncthreads();
    for (int off = 1; off < 1024; off <<= 1) {
        int v = (t >= off) ? sums[t - off] : 0;
        __syncthreads();
        sums[t] += v;
        __syncthreads();
    }
    int offset = (t > 0) ? sums[t - 1] : 0;
#pragma unroll
    for (int i = 0; i < CH; i++) {
        int gi = base + i;
        if (gi < NN) g_rowptr[gi] = offset + local[i];
    }
    if (t == 1023) g_rowptr[NN] = sums[1023];
}

// ---------------- fused preprocessing #2: CSR scatter + self-loop attrs ----------------
__global__ void k_scatself(const int* __restrict__ eidx) {
    int i = blockIdx.x * blockDim.x + threadIdx.x;
    if (i < ET) {
        int s, d;
        if (i < EE) { s = eidx[i]; d = eidx[EE + i]; }
        else        { s = i - EE;  d = s; }
        int pos  = atomicAdd(&g_cursor[d], 1);
        int slot = g_rowptr[d] + pos;
        g_src[slot]  = s;
        g_eids[slot] = i;
    }
    if (i < NN) {
        int dg = g_deg[i];
        float inv = 1.f / fmaxf((float)dg, 1.f);
#pragma unroll
        for (int k = 0; k < EIN; k++)
            g_selfA[i * 17 + k] = g_asum[i * EIN + k] * inv;
        g_selfA[i * 17 + 16] = (dg > 0) ? 1.f : 0.f;
    }
}

// duplicated-pair edge coeffs in CSR order
__global__ void k_ea(const float* __restrict__ eattr) {
    int i = blockIdx.x * blockDim.x + threadIdx.x;
    if (i >= ET * 17) return;
    int slot = i / 17, k = i - slot * 17;
    int eid = g_eids[slot];
    float v;
    if (eid < EE) v = (k < 16) ? eattr[eid * 16 + k] : 1.f;
    else          v = g_selfA[(eid - EE) * 17 + k];
    g_ea2[(size_t)slot * 18 + k] = dupf(v);
}

// ---------------- GEMM: g_xlr = h @ [Wl | Wr] + bias, f32x2 inner ----------------
#define GM 128
#define GN 64
#define GK 32

__global__ void __launch_bounds__(256) k_gemm2(int hinIdx,
                                               const float* __restrict__ WL, const float* __restrict__ bL,
                                               const float* __restrict__ WR, const float* __restrict__ bR) {
    __shared__ __align__(16) float Ast[GK][GM + 4];
    __shared__ __align__(16) float Bs[GK][GN];
    const float* H = g_h[hinIdx];
    int by = blockIdx.y;
    const float* W; const float* bias; int colOff;
    if (by < 8) { W = WL; bias = bL; colOff = 0; }
    else        { W = WR; bias = bR; colOff = 512; by -= 8; }
    int bm = blockIdx.x * GM, bn = by * GN;
    int tid = threadIdx.x;
    int tm = (tid >> 4) * 8;
    int tn = (tid & 15) * 4;

    u64 acc[4][4];
#pragma unroll
    for (int p = 0; p < 4; p++)
#pragma unroll
        for (int n = 0; n < 4; n++) acc[p][n] = 0ull;

    int lm = tid >> 3;
    int lk = (tid & 7) * 4;
    int brw = tid >> 4;
    int bc  = (tid & 15) * 4;

    for (int k0 = 0; k0 < 128; k0 += GK) {
#pragma unroll
        for (int i = 0; i < 4; i++) {
            int m = lm + i * 32;
            int gr = bm + m;
            float4 av = make_float4(0.f, 0.f, 0.f, 0.f);
            if (gr < NN) av = *(const float4*)(H + gr * 128 + k0 + lk);
            Ast[lk + 0][m] = av.x; Ast[lk + 1][m] = av.y;
            Ast[lk + 2][m] = av.z; Ast[lk + 3][m] = av.w;
        }
#pragma unroll
        for (int i = 0; i < 2; i++) {
            int r = brw + i * 16;
            *(float4*)&Bs[r][bc] = *(const float4*)(W + (k0 + r) * 512 + bn + bc);
        }
        __syncthreads();
#pragma unroll
        for (int kk = 0; kk < GK; kk++) {
            ulonglong2 p0 = *(const ulonglong2*)&Ast[kk][tm];
            ulonglong2 p1 = *(const ulonglong2*)&Ast[kk][tm + 4];
            u64 a0 = p0.x, a1 = p0.y, a2 = p1.x, a3 = p1.y;
            float4 b = *(const float4*)&Bs[kk][tn];
            u64 b0 = dupf(b.x), b1 = dupf(b.y), b2 = dupf(b.z), b3 = dupf(b.w);
            acc[0][0] = fma2(a0, b0, acc[0][0]); acc[0][1] = fma2(a0, b1, acc[0][1]);
            acc[0][2] = fma2(a0, b2, acc[0][2]); acc[0][3] = fma2(a0, b3, acc[0][3]);
            acc[1][0] = fma2(a1, b0, acc[1][0]); acc[1][1] = fma2(a1, b1, acc[1][1]);
            acc[1][2] = fma2(a1, b2, acc[1][2]); acc[1][3] = fma2(a1, b3, acc[1][3]);
            acc[2][0] = fma2(a2, b0, acc[2][0]); acc[2][1] = fma2(a2, b1, acc[2][1]);
            acc[2][2] = fma2(a2, b2, acc[2][2]); acc[2][3] = fma2(a2, b3, acc[2][3]);
            acc[3][0] = fma2(a3, b0, acc[3][0]); acc[3][1] = fma2(a3, b1, acc[3][1]);
            acc[3][2] = fma2(a3, b2, acc[3][2]); acc[3][3] = fma2(a3, b3, acc[3][3]);
        }
        __syncthreads();
    }

    float4 bv = *(const float4*)(bias + bn + tn);
#pragma unroll
    for (int p = 0; p < 4; p++) {
        float c0[4], c1[4];
#pragma unroll
        for (int n = 0; n < 4; n++) upk(acc[p][n], c0[n], c1[n]);
        int r0 = bm + tm + 2 * p, r1 = r0 + 1;
        if (r0 < NN) {
            float4 o = make_float4(c0[0] + bv.x, c0[1] + bv.y, c0[2] + bv.z, c0[3] + bv.w);
            *(float4*)(g_xlr + (size_t)r0 * 1024 + colOff + bn + tn) = o;
        }
        if (r1 < NN) {
            float4 o = make_float4(c1[0] + bv.x, c1[1] + bv.y, c1[2] + bv.z, c1[3] + bv.w);
            *(float4*)(g_xlr + (size_t)r1 * 1024 + colOff + bn + tn) = o;
        }
    }
}

// ---------------- fused GATv2 aggregation, f32x2 ----------------
// outp==nullptr -> write g_h[outSel] (resolved in DEVICE code; round-2/3 bug was
// passing the host shadow address of g_h from host code)
__global__ void __launch_bounds__(128) k_agg(const float* __restrict__ att_l,
                                             const float* __restrict__ bias_l,
                                             int lM, float* __restrict__ outp, int outSel) {
    int v = blockIdx.x;
    int t = threadIdx.x;
    int w = t >> 5, lam = t & 31;
    int jbase = w * HID + lam * 4;

    const float* Ml = g_M + lM * (17 * 512);
    u64 M0[17], M1[17];
#pragma unroll
    for (int k = 0; k < 17; k++) ldg2(Ml + k * 512 + jbase, M0[k], M1[k]);

    float4 attv = *(const float4*)(att_l + jbase);
    u64 xr0, xr1; ldg2(g_xlr + (size_t)v * 1024 + 512 + jbase, xr0, xr1);

    u64 acc0 = 0ull, acc1 = 0ull;
    float rmax = -INFINITY, denom = 0.f;

    int beg = g_rowptr[v], end = g_rowptr[v + 1];
    for (int i = beg; i < end; i++) {
        int s = g_src[i];
        const u64* ea = g_ea2 + (size_t)i * 18;
        u64 xl0, xl1; ldg2(g_xlr + (size_t)s * 1024 + jbase, xl0, xl1);
        u64 m0 = add2(xr0, xl0), m1 = add2(xr1, xl1);
#pragma unroll
        for (int q = 0; q < 8; q++) {
            u64 e0, e1; ldg2(ea + 2 * q, e0, e1);
            m0 = fma2(e0, M0[2 * q], m0);     m1 = fma2(e0, M1[2 * q], m1);
            m0 = fma2(e1, M0[2 * q + 1], m0); m1 = fma2(e1, M1[2 * q + 1], m1);
        }
        {
            u64 e16 = ldg1(ea + 16);
            m0 = fma2(e16, M0[16], m0); m1 = fma2(e16, M1[16], m1);
        }
        float f0, f1, f2, f3; upk(m0, f0, f1); upk(m1, f2, f3);
        f0 = fmaxf(f0, 0.f) + NEGS * fminf(f0, 0.f);
        f1 = fmaxf(f1, 0.f) + NEGS * fminf(f1, 0.f);
        f2 = fmaxf(f2, 0.f) + NEGS * fminf(f2, 0.f);
        f3 = fmaxf(f3, 0.f) + NEGS * fminf(f3, 0.f);
        float part = f0 * attv.x + f1 * attv.y + f2 * attv.z + f3 * attv.w;
#pragma unroll
        for (int o = 16; o; o >>= 1)
            part += __shfl_xor_sync(0xffffffffu, part, o);
        float nm = fmaxf(rmax, part);
        float sc = __expf(rmax - nm);
        float p  = __expf(part - nm);
        denom = denom * sc + p;
        u64 scd = dupf(sc), pd = dupf(p);
        acc0 = fma2(pd, xl0, mul2(acc0, scd));
        acc1 = fma2(pd, xl1, mul2(acc1, scd));
        rmax = nm;
    }

    __shared__ float sred[HEADS][HID];
    float inv = 1.f / denom;
    float a0, a1, a2, a3; upk(acc0, a0, a1); upk(acc1, a2, a3);
    sred[w][lam * 4 + 0] = a0 * inv;
    sred[w][lam * 4 + 1] = a1 * inv;
    sred[w][lam * 4 + 2] = a2 * inv;
    sred[w][lam * 4 + 3] = a3 * inv;
    __syncthreads();
    float o = (sred[0][t] + sred[1][t] + sred[2][t] + sred[3][t]) * 0.25f + bias_l[t];
    float* dst = outp ? outp : g_h[outSel];
    dst[(size_t)v * HID + t] = fmaxf(o, 0.f);
}

// ---------------- launch ----------------
extern "C" void kernel_launch(void* const* d_in, const int* in_sizes, int n_in,
                              void* d_out, int out_size) {
    const float* x       = (const float*)d_in[0];
    const int*   eidx    = (const int*)  d_in[1];
    const float* eattr   = (const float*)d_in[2];
    const float* node_W  = (const float*)d_in[3];
    const float* node_b  = (const float*)d_in[4];
    const float* edge_W  = (const float*)d_in[5];
    const float* edge_b  = (const float*)d_in[6];
    const float* Wl      = (const float*)d_in[7];
    const float* bl      = (const float*)d_in[8];
    const float* Wr      = (const float*)d_in[9];
    const float* br      = (const float*)d_in[10];
    const float* We      = (const float*)d_in[11];
    const float* att     = (const float*)d_in[12];
    const float* bias    = (const float*)d_in[13];
    float* out = (float*)d_out;

    k_pre<<<ZB + CB + EB, 128>>>(x, node_W, node_b, edge_W, edge_b, We);   // 1
    k_deg<<<(EE * EIN + 255) / 256, 256>>>(eattr, eidx);                    // 2
    k_scan<<<1, 1024>>>();                                                  // 3
    k_scatself<<<(ET + 255) / 256, 256>>>(eidx);                            // 4
    k_ea<<<(ET * 17 + 255) / 256, 256>>>(eattr);                            // 5

    dim3 gdim((NN + GM - 1) / GM, 16);
    int hin = 0;
    for (int l = 0; l < 3; l++) {
        k_gemm2<<<gdim, 256>>>(hin,                                         // 6 = layer-0 GEMM (ncu target)
                               Wl + (size_t)l * 128 * 512, bl + l * 512,
                               Wr + (size_t)l * 128 * 512, br + l * 512);
        if (l == 2)
            k_agg<<<NN, 128>>>(att + l * HEADS * HID, bias + l * HID, l, out, 0);
        else
            k_agg<<<NN, 128>>>(att + l * HEADS * HID, bias + l * HID, l, (float*)nullptr, 1 - hin);
        hin = 1 - hin;
    }
}

// round 5
// speedup vs baseline: 1.1227x; 1.1227x over previous
#include <cuda_runtime.h>
#include <math.h>

#define NN 10000
#define EE 160000
#define ET (EE + NN)
#define EIN 16
#define HID 128
#define HEADS 4
#define NEGS 0.2f

typedef unsigned long long u64;

// ---------------- f32x2 helpers (pure register ops) ----------------
__device__ __forceinline__ u64 dupf(float v) {
    u64 r; unsigned u = __float_as_uint(v);
    asm("mov.b64 %0, {%1,%2};" : "=l"(r) : "r"(u), "r"(u));
    return r;
}
__device__ __forceinline__ void upk(u64 p, float& lo, float& hi) {
    unsigned a, b;
    asm("mov.b64 {%0,%1}, %2;" : "=r"(a), "=r"(b) : "l"(p));
    lo = __uint_as_float(a); hi = __uint_as_float(b);
}
__device__ __forceinline__ u64 fma2(u64 a, u64 b, u64 c) {
    u64 d; asm("fma.rn.f32x2 %0, %1, %2, %3;" : "=l"(d) : "l"(a), "l"(b), "l"(c));
    return d;
}

// ---------------- scratch (zero at module load; k_clean restores zeros each launch) ----------------
__device__ float g_h[2][NN * HID];
__device__ float g_xlr[NN * 1024];
__device__ float g_asum[NN * EIN];
__device__ int   g_deg[NN];
__device__ int   g_cursor[NN];
__device__ __align__(16) float g_selfA[NN * 20];   // padded self-loop coeffs (16 attrs + bias flag)
__device__ int   g_rowptr[NN + 1];
__device__ int   g_src[ET];
__device__ int   g_eids[ET];
__device__ float g_M[3 * 17 * 512];

// ---------------- preprocessing #1: compose M + node embedding ----------------
#define CB 204           // 204*128 = 26112 = 3*17*512
#define EB 625           // 625*16  = 10000

__global__ void __launch_bounds__(128) k_pre(const float* __restrict__ x,
                                             const float* __restrict__ Wn,
                                             const float* __restrict__ bn,
                                             const float* __restrict__ edge_W,
                                             const float* __restrict__ edge_b,
                                             const float* __restrict__ We) {
    __shared__ float xs[16][64];
    int b = blockIdx.x, tid = threadIdx.x;
    if (b < CB) {
        int idx = b * 128 + tid;
        int l = idx / (17 * 512);
        int r = idx - l * (17 * 512);
        int k = r >> 9;
        int j = r & 511;
        const float* wp = We + l * 128 * 512 + j;
        float acc = 0.f;
#pragma unroll 8
        for (int t = 0; t < 128; t++) {
            float ev = (k < 16) ? edge_W[k * 128 + t] : edge_b[t];
            acc += ev * wp[t * 512];
        }
        g_M[idx] = acc;
        return;
    }
    int nb = (b - CB) * 16;
#pragma unroll
    for (int i = 0; i < 8; i++) {
        int idx = tid + i * 128;
        int r = idx >> 6, c = idx & 63;
        xs[r][c] = x[(nb + r) * 64 + c];
    }
    __syncthreads();
    int c = tid;
    float acc[16];
#pragma unroll
    for (int n = 0; n < 16; n++) acc[n] = 0.f;
    for (int k = 0; k < 64; k++) {
        float wv = Wn[k * 128 + c];
#pragma unroll
        for (int n = 0; n < 16; n++) acc[n] += xs[n][k] * wv;
    }
    float bb = bn[c];
#pragma unroll
    for (int n = 0; n < 16; n++)
        g_h[0][(nb + n) * 128 + c] = acc[n] + bb;
}

// ---------------- degree + edge_attr segment sums (g_asum/g_deg are pre-zeroed) ----------------
__global__ void k_deg(const float* __restrict__ eattr, const int* __restrict__ eidx) {
    int i = blockIdx.x * blockDim.x + threadIdx.x;
    if (i >= EE * EIN) return;
    int e = i >> 4, k = i & 15;
    int d = eidx[EE + e];
    atomicAdd(&g_asum[d * EIN + k], eattr[i]);
    if (k == 0) atomicAdd(&g_deg[d], 1);
}

__global__ void k_scan() {
    __shared__ int sums[1024];
    int t = threadIdx.x;
    const int CH = 10;
    int base = t * CH;
    int local[CH];
    int run = 0;
#pragma unroll
    for (int i = 0; i < CH; i++) {
        int gi = base + i;
        int v = (gi < NN) ? (g_deg[gi] + 1) : 0;
        local[i] = run;
        run += v;
    }
    sums[t] = run;
    __syncthreads();
    for (int off = 1; off < 1024; off <<= 1) {
        int v = (t >= off) ? sums[t - off] : 0;
        __syncthreads();
        sums[t] += v;
        __syncthreads();
    }
    int offset = (t > 0) ? sums[t - 1] : 0;
#pragma unroll
    for (int i = 0; i < CH; i++) {
        int gi = base + i;
        if (gi < NN) g_rowptr[gi] = offset + local[i];
    }
    if (t == 1023) g_rowptr[NN] = sums[1023];
}

// ---------------- CSR scatter + padded self-loop attrs ----------------
__global__ void k_scatself(const int* __restrict__ eidx) {
    int i = blockIdx.x * blockDim.x + threadIdx.x;
    if (i < ET) {
        int s, d;
        if (i < EE) { s = eidx[i]; d = eidx[EE + i]; }
        else        { s = i - EE;  d = s; }
        int pos  = atomicAdd(&g_cursor[d], 1);
        int slot = g_rowptr[d] + pos;
        g_src[slot]  = s;
        g_eids[slot] = i;
    }
    if (i < NN) {
        int dg = g_deg[i];
        float inv = 1.f / fmaxf((float)dg, 1.f);
#pragma unroll
        for (int k = 0; k < EIN; k++)
            g_selfA[i * 20 + k] = g_asum[i * EIN + k] * inv;
        g_selfA[i * 20 + 16] = (dg > 0) ? 1.f : 0.f;
        g_selfA[i * 20 + 17] = 0.f; g_selfA[i * 20 + 18] = 0.f; g_selfA[i * 20 + 19] = 0.f;
    }
}

// ---------------- cleanup: restore zero invariant for next replay ----------------
__global__ void k_clean() {
    int i = blockIdx.x * blockDim.x + threadIdx.x;
    if (i < NN * EIN) g_asum[i] = 0.f;
    if (i < NN) { g_deg[i] = 0; g_cursor[i] = 0; }
}

// ---------------- GEMM: g_xlr = h @ [Wl | Wr] + bias, f32x2 inner ----------------
#define GM 128
#define GN 64
#define GK 32

__global__ void __launch_bounds__(256) k_gemm2(int hinIdx,
                                               const float* __restrict__ WL, const float* __restrict__ bL,
                                               const float* __restrict__ WR, const float* __restrict__ bR) {
    __shared__ __align__(16) float Ast[GK][GM + 4];
    __shared__ __align__(16) float Bs[GK][GN];
    const float* H = g_h[hinIdx];
    int by = blockIdx.y;
    const float* W; const float* bias; int colOff;
    if (by < 8) { W = WL; bias = bL; colOff = 0; }
    else        { W = WR; bias = bR; colOff = 512; by -= 8; }
    int bm = blockIdx.x * GM, bn = by * GN;
    int tid = threadIdx.x;
    int tm = (tid >> 4) * 8;
    int tn = (tid & 15) * 4;

    u64 acc[4][4];
#pragma unroll
    for (int p = 0; p < 4; p++)
#pragma unroll
        for (int n = 0; n < 4; n++) acc[p][n] = 0ull;

    int lm = tid >> 3;
    int lk = (tid & 7) * 4;
    int brw = tid >> 4;
    int bc  = (tid & 15) * 4;

    for (int k0 = 0; k0 < 128; k0 += GK) {
#pragma unroll
        for (int i = 0; i < 4; i++) {
            int m = lm + i * 32;
            int gr = bm + m;
            float4 av = make_float4(0.f, 0.f, 0.f, 0.f);
            if (gr < NN) av = *(const float4*)(H + gr * 128 + k0 + lk);
            Ast[lk + 0][m] = av.x; Ast[lk + 1][m] = av.y;
            Ast[lk + 2][m] = av.z; Ast[lk + 3][m] = av.w;
        }
#pragma unroll
        for (int i = 0; i < 2; i++) {
            int r = brw + i * 16;
            *(float4*)&Bs[r][bc] = *(const float4*)(W + (k0 + r) * 512 + bn + bc);
        }
        __syncthreads();
#pragma unroll
        for (int kk = 0; kk < GK; kk++) {
            ulonglong2 p0 = *(const ulonglong2*)&Ast[kk][tm];
            ulonglong2 p1 = *(const ulonglong2*)&Ast[kk][tm + 4];
            u64 a0 = p0.x, a1 = p0.y, a2 = p1.x, a3 = p1.y;
            float4 b = *(const float4*)&Bs[kk][tn];
            u64 b0 = dupf(b.x), b1 = dupf(b.y), b2 = dupf(b.z), b3 = dupf(b.w);
            acc[0][0] = fma2(a0, b0, acc[0][0]); acc[0][1] = fma2(a0, b1, acc[0][1]);
            acc[0][2] = fma2(a0, b2, acc[0][2]); acc[0][3] = fma2(a0, b3, acc[0][3]);
            acc[1][0] = fma2(a1, b0, acc[1][0]); acc[1][1] = fma2(a1, b1, acc[1][1]);
            acc[1][2] = fma2(a1, b2, acc[1][2]); acc[1][3] = fma2(a1, b3, acc[1][3]);
            acc[2][0] = fma2(a2, b0, acc[2][0]); acc[2][1] = fma2(a2, b1, acc[2][1]);
            acc[2][2] = fma2(a2, b2, acc[2][2]); acc[2][3] = fma2(a2, b3, acc[2][3]);
            acc[3][0] = fma2(a3, b0, acc[3][0]); acc[3][1] = fma2(a3, b1, acc[3][1]);
            acc[3][2] = fma2(a3, b2, acc[3][2]); acc[3][3] = fma2(a3, b3, acc[3][3]);
        }
        __syncthreads();
    }

    float4 bv = *(const float4*)(bias + bn + tn);
#pragma unroll
    for (int p = 0; p < 4; p++) {
        float c0[4], c1[4];
#pragma unroll
        for (int n = 0; n < 4; n++) upk(acc[p][n], c0[n], c1[n]);
        int r0 = bm + tm + 2 * p, r1 = r0 + 1;
        if (r0 < NN) {
            float4 o = make_float4(c0[0] + bv.x, c0[1] + bv.y, c0[2] + bv.z, c0[3] + bv.w);
            *(float4*)(g_xlr + (size_t)r0 * 1024 + colOff + bn + tn) = o;
        }
        if (r1 < NN) {
            float4 o = make_float4(c1[0] + bv.x, c1[1] + bv.y, c1[2] + bv.z, c1[3] + bv.w);
            *(float4*)(g_xlr + (size_t)r1 * 1024 + colOff + bn + tn) = o;
        }
    }
}

// ---------------- GATv2 aggregation: chunked two-phase softmax (no per-edge serial chain) ----------------
__global__ void __launch_bounds__(128) k_agg(const float* __restrict__ att_l,
                                             const float* __restrict__ bias_l,
                                             const float* __restrict__ eattr,
                                             int lM, float* __restrict__ outp, int outSel) {
    int v = blockIdx.x;
    int t = threadIdx.x;
    int w = t >> 5, lam = t & 31;
    int jbase = w * HID + lam * 4;

    const float* Ml = g_M + lM * (17 * 512);
    float4 Mreg[17];
#pragma unroll
    for (int k = 0; k < 17; k++) Mreg[k] = *(const float4*)(Ml + k * 512 + jbase);

    float4 attv = *(const float4*)(att_l + jbase);
    float4 xrv  = *(const float4*)(g_xlr + (size_t)v * 1024 + 512 + jbase);

    float acc0 = 0.f, acc1 = 0.f, acc2 = 0.f, acc3 = 0.f;
    float rmax = -INFINITY, denom = 0.f;

    int beg = g_rowptr[v], end = g_rowptr[v + 1];
    for (int c0 = beg; c0 < end; c0 += 32) {
        int cnt = min(32, end - c0);
        int my_s = 0, my_e = 0;
        if (lam < cnt) { my_s = g_src[c0 + lam]; my_e = g_eids[c0 + lam]; }
        float my_logit = -INFINITY;

        // phase 1: independent logits (pipelined; no cross-edge dependency)
        for (int i = 0; i < cnt; i++) {
            int s   = __shfl_sync(0xffffffffu, my_s, i);
            int eid = __shfl_sync(0xffffffffu, my_e, i);
            float ea[17];
            if (eid < EE) {
                const float4* p = (const float4*)(eattr + (size_t)eid * 16);
                float4 a0 = p[0], a1 = p[1], a2 = p[2], a3 = p[3];
                ea[0] = a0.x; ea[1] = a0.y; ea[2]  = a0.z; ea[3]  = a0.w;
                ea[4] = a1.x; ea[5] = a1.y; ea[6]  = a1.z; ea[7]  = a1.w;
                ea[8] = a2.x; ea[9] = a2.y; ea[10] = a2.z; ea[11] = a2.w;
                ea[12] = a3.x; ea[13] = a3.y; ea[14] = a3.z; ea[15] = a3.w;
                ea[16] = 1.f;
            } else {
                const float4* p = (const float4*)(g_selfA + (size_t)(eid - EE) * 20);
                float4 a0 = p[0], a1 = p[1], a2 = p[2], a3 = p[3];
                float4 a4 = p[4];
                ea[0] = a0.x; ea[1] = a0.y; ea[2]  = a0.z; ea[3]  = a0.w;
                ea[4] = a1.x; ea[5] = a1.y; ea[6]  = a1.z; ea[7]  = a1.w;
                ea[8] = a2.x; ea[9] = a2.y; ea[10] = a2.z; ea[11] = a2.w;
                ea[12] = a3.x; ea[13] = a3.y; ea[14] = a3.z; ea[15] = a3.w;
                ea[16] = a4.x;
            }
            float4 xl = *(const float4*)(g_xlr + (size_t)s * 1024 + jbase);
            float m0 = xrv.x + xl.x, m1 = xrv.y + xl.y;
            float m2 = xrv.z + xl.z, m3 = xrv.w + xl.w;
#pragma unroll
            for (int k = 0; k < 17; k++) {
                m0 += ea[k] * Mreg[k].x; m1 += ea[k] * Mreg[k].y;
                m2 += ea[k] * Mreg[k].z; m3 += ea[k] * Mreg[k].w;
            }
            m0 = fmaxf(m0, 0.f) + NEGS * fminf(m0, 0.f);
            m1 = fmaxf(m1, 0.f) + NEGS * fminf(m1, 0.f);
            m2 = fmaxf(m2, 0.f) + NEGS * fminf(m2, 0.f);
            m3 = fmaxf(m3, 0.f) + NEGS * fminf(m3, 0.f);
            float part = m0 * attv.x + m1 * attv.y + m2 * attv.z + m3 * attv.w;
#pragma unroll
            for (int o = 16; o; o >>= 1)
                part += __shfl_xor_sync(0xffffffffu, part, o);
            if (lam == i) my_logit = part;
        }

        // chunk softmax merge (serial work once per chunk, not per edge)
        float cmax = my_logit;
#pragma unroll
        for (int o = 16; o; o >>= 1)
            cmax = fmaxf(cmax, __shfl_xor_sync(0xffffffffu, cmax, o));
        float nm = fmaxf(rmax, cmax);
        float myp = (lam < cnt) ? __expf(my_logit - nm) : 0.f;
        float psum = myp;
#pragma unroll
        for (int o = 16; o; o >>= 1)
            psum += __shfl_xor_sync(0xffffffffu, psum, o);
        float sc = __expf(rmax - nm);        // 0 on first chunk (rmax=-inf)
        denom = denom * sc + psum;
        acc0 *= sc; acc1 *= sc; acc2 *= sc; acc3 *= sc;

        // phase 2: dependency-free weighted accumulation (regather hits L1/L2)
        for (int i = 0; i < cnt; i++) {
            float p = __shfl_sync(0xffffffffu, myp, i);
            int s   = __shfl_sync(0xffffffffu, my_s, i);
            float4 xl = *(const float4*)(g_xlr + (size_t)s * 1024 + jbase);
            acc0 += p * xl.x; acc1 += p * xl.y; acc2 += p * xl.z; acc3 += p * xl.w;
        }
        rmax = nm;
    }

    __shared__ float sred[HEADS][HID];
    float inv = 1.f / denom;
    sred[w][lam * 4 + 0] = acc0 * inv;
    sred[w][lam * 4 + 1] = acc1 * inv;
    sred[w][lam * 4 + 2] = acc2 * inv;
    sred[w][lam * 4 + 3] = acc3 * inv;
    __syncthreads();
    float o = (sred[0][t] + sred[1][t] + sred[2][t] + sred[3][t]) * 0.25f + bias_l[t];
    float* dst = outp ? outp : g_h[outSel];
    dst[(size_t)v * HID + t] = fmaxf(o, 0.f);
}

// ---------------- launch ----------------
extern "C" void kernel_launch(void* const* d_in, const int* in_sizes, int n_in,
                              void* d_out, int out_size) {
    const float* x       = (const float*)d_in[0];
    const int*   eidx    = (const int*)  d_in[1];
    const float* eattr   = (const float*)d_in[2];
    const float* node_W  = (const float*)d_in[3];
    const float* node_b  = (const float*)d_in[4];
    const float* edge_W  = (const float*)d_in[5];
    const float* edge_b  = (const float*)d_in[6];
    const float* Wl      = (const float*)d_in[7];
    const float* bl      = (const float*)d_in[8];
    const float* Wr      = (const float*)d_in[9];
    const float* br      = (const float*)d_in[10];
    const float* We      = (const float*)d_in[11];
    const float* att     = (const float*)d_in[12];
    const float* bias    = (const float*)d_in[13];
    float* out = (float*)d_out;

    dim3 gdim((NN + GM - 1) / GM, 16);

    k_pre<<<CB + EB, 128>>>(x, node_W, node_b, edge_W, edge_b, We);         // 1
    k_deg<<<(EE * EIN + 255) / 256, 256>>>(eattr, eidx);                     // 2
    k_scan<<<1, 1024>>>();                                                   // 3
    k_gemm2<<<gdim, 256>>>(0, Wl, bl, Wr, br);                               // 4  <- ncu target (layer-0 GEMM)
    k_scatself<<<(ET + 255) / 256, 256>>>(eidx);                             // 5
    k_agg<<<NN, 128>>>(att, bias, eattr, 0, (float*)nullptr, 1);             // 6  layer 0 -> g_h[1]
    k_gemm2<<<gdim, 256>>>(1, Wl + (size_t)1 * 128 * 512, bl + 512,          // 7
                           Wr + (size_t)1 * 128 * 512, br + 512);
    k_agg<<<NN, 128>>>(att + HEADS * HID, bias + HID, eattr, 1,              // 8  layer 1 -> g_h[0]
                       (float*)nullptr, 0);
    k_gemm2<<<gdim, 256>>>(0, Wl + (size_t)2 * 128 * 512, bl + 1024,         // 9
                           Wr + (size_t)2 * 128 * 512, br + 1024);
    k_agg<<<NN, 128>>>(att + 2 * HEADS * HID, bias + 2 * HID, eattr, 2,      // 10 layer 2 -> out
                       out, 0);
    k_clean<<<(NN * EIN + 255) / 256, 256>>>();                              // 11 restore zero invariant
}